// round 14
// baseline (speedup 1.0000x reference)
#include <cuda_runtime.h>

#define N_NODES 100000
#define E_EDGES 1600000
#define FIN  16
#define FMID 32
#define FOUT 16
#define CAP  64                            // padded per-node capacity (mean deg 16)
#define NBLK 888                           // 6 blocks/SM on 148 SMs — co-residency guaranteed
#define NTHR 256
#define NGRP (N_NODES / 16)                // 6250 groups of 16 nodes

// ---------------- device scratch ----------------
__device__ int   g_cnt[N_NODES];           // arrival counter (0 at replay start)
__device__ int   g_degc[N_NODES];          // min(deg, CAP) snapshot
__device__ float g_dinv[N_NODES];
__device__ int   g_psrow[N_NODES * CAP];   // padded adjacency, stores r*16 (premultiplied)
__device__ int   g_spill_r[E_EDGES];       // overflow (premultiplied r*16)
__device__ int   g_spill_c[E_EDGES];
__device__ int   g_spill_cursor;           // 0 at replay start
__device__ int   g_spill_n;
__device__ float g_xs [N_NODES * FIN];     // x * dinv  (layer-1 gather source)
__device__ float g_h2s[N_NODES * FOUT];    // (relu(o1) @ W2) * dinv
__device__ int   g_bar[3];                 // grid-barrier counters (reset by k_binit)

// Monotonic-counter grid barrier (counters zeroed per replay by k_binit).
__device__ __forceinline__ void grid_barrier(int slot) {
    __syncthreads();
    if (threadIdx.x == 0) {
        __threadfence();                               // release writes
        atomicAdd(&g_bar[slot], 1);
        while (*(volatile int*)&g_bar[slot] < NBLK) __nanosleep(64);
        __threadfence();                               // acquire others' writes
    }
    __syncthreads();
}

__global__ void k_binit() {
    if (threadIdx.x < 3) g_bar[threadIdx.x] = 0;
}

__global__ void __launch_bounds__(NTHR, 6)
k_mega(const unsigned int* __restrict__ words,
       const void* __restrict__ edge_raw, int E,
       const float* __restrict__ x,
       const float* __restrict__ W1, const float* __restrict__ b1,
       const float* __restrict__ W2, const float* __restrict__ b2,
       const float* __restrict__ fcW, const float* __restrict__ fcb,
       float* __restrict__ out) {
    __shared__ float sW1[FIN * FMID];
    __shared__ float sW2[FMID * FOUT];
    __shared__ float sb1[FMID];
    __shared__ float sagg[16][FIN];
    __shared__ float so1[16][FMID];
    __shared__ unsigned int s_or;

    // ---- dtype detect (every block, same 512 words -> identical decision)
    if (threadIdx.x == 0) s_or = 0u;
    __syncthreads();
    {
        unsigned int acc = words[2 * threadIdx.x + 1] |
                           words[2 * (threadIdx.x + 256) + 1];
        #pragma unroll
        for (int s = 16; s > 0; s >>= 1)
            acc |= __shfl_xor_sync(0xffffffffu, acc, s);
        if ((threadIdx.x & 31) == 0) atomicOr(&s_or, acc);
    }
    __syncthreads();
    const int is64 = (s_or == 0u) ? 1 : 0;

    // =========== phase 1: padded-CSR build (premultiplied indices) ===========
    {
        int nquad = (E + 3) >> 2;
        for (int t = blockIdx.x * NTHR + threadIdx.x; t < nquad; t += NBLK * NTHR) {
            int base = t * 4;
            int n = min(4, E - base);
            int r[4], c[4];
            if (n == 4) {
                if (is64) {
                    const longlong2* p2 = (const longlong2*)edge_raw;
                    longlong2 ra = __ldg(&p2[(base >> 1)]);
                    longlong2 rb = __ldg(&p2[(base >> 1) + 1]);
                    longlong2 ca = __ldg(&p2[((E + base) >> 1)]);
                    longlong2 cb = __ldg(&p2[((E + base) >> 1) + 1]);
                    r[0] = (int)ra.x; r[1] = (int)ra.y; r[2] = (int)rb.x; r[3] = (int)rb.y;
                    c[0] = (int)ca.x; c[1] = (int)ca.y; c[2] = (int)cb.x; c[3] = (int)cb.y;
                } else {
                    const int4* p4 = (const int4*)edge_raw;
                    int4 rv = __ldg(&p4[base >> 2]);
                    int4 cv = __ldg(&p4[(E + base) >> 2]);
                    r[0] = rv.x; r[1] = rv.y; r[2] = rv.z; r[3] = rv.w;
                    c[0] = cv.x; c[1] = cv.y; c[2] = cv.z; c[3] = cv.w;
                }
            } else {
                #pragma unroll
                for (int k = 0; k < 4; k++) if (k < n) {
                    if (is64) {
                        const long long* p = (const long long*)edge_raw;
                        r[k] = (int)p[base + k];  c[k] = (int)p[E + base + k];
                    } else {
                        const int* p = (const int*)edge_raw;
                        r[k] = p[base + k];       c[k] = p[E + base + k];
                    }
                }
            }
            int rank[4];
            #pragma unroll
            for (int k = 0; k < 4; k++) if (k < n)
                rank[k] = atomicAdd(&g_cnt[c[k]], 1);
            #pragma unroll
            for (int k = 0; k < 4; k++) if (k < n) {
                if (rank[k] < CAP) {
                    g_psrow[c[k] * CAP + rank[k]] = r[k] * 16;   // premultiplied
                } else {
                    int s = atomicAdd(&g_spill_cursor, 1);
                    g_spill_c[s] = c[k];
                    g_spill_r[s] = r[k] * 16;
                }
            }
        }
    }
    grid_barrier(0);

    // =========== phase 2: dinv + xs = x*dinv + counter snapshot/reset ===========
    if (blockIdx.x == 0 && threadIdx.x == 0) {
        g_spill_n = g_spill_cursor;
        g_spill_cursor = 0;
    }
    for (int idx = blockIdx.x * NTHR + threadIdx.x; idx < N_NODES * FIN;
         idx += NBLK * NTHR) {
        int i = idx >> 4;
        int f = idx & 15;
        int deg = g_cnt[i];                 // all 16 lanes read before lane-0 resets
        float d = rsqrtf((float)(deg + 1)); // +1 self-loop
        __syncwarp();
        if (f == 0) {
            g_dinv[i] = d;
            g_degc[i] = min(deg, CAP);
            g_cnt[i]  = 0;                  // ready for next replay
        }
        g_xs[idx] = __ldg(&x[idx]) * d;
    }
    grid_barrier(1);

    // =========== phase 3: gather1 (input space) + W1 + relu + W2 ===========
    for (int t = threadIdx.x; t < FIN * FMID; t += NTHR) {
        sW1[t] = W1[t];
        sW2[t] = W2[t];
    }
    for (int t = threadIdx.x; t < FMID; t += NTHR) sb1[t] = b1[t];
    __syncthreads();

    const int f = threadIdx.x & 15;
    const int h = threadIdx.x >> 4;          // node slot in block (0..15)
    const int sn = g_spill_n;                // 0 for this input

    for (int g = blockIdx.x; g < NGRP; g += NBLK) {
        int w = g * 16 + h;
        const int4* adj4 = (const int4*)&g_psrow[w * CAP];
        int deg = g_degc[w];
        float d = g_dinv[w];

        float acc0 = g_xs[w * FIN + f];      // self-loop
        float acc1 = 0.0f;
        int j = 0;
        for (; j + 8 <= deg; j += 8) {
            int4 ia = __ldg(&adj4[j >> 2]);
            int4 ib = __ldg(&adj4[(j >> 2) + 1]);
            float a0 = __ldg(&g_xs[ia.x + f]);
            float a1 = __ldg(&g_xs[ia.y + f]);
            float a2 = __ldg(&g_xs[ia.z + f]);
            float a3 = __ldg(&g_xs[ia.w + f]);
            float a4 = __ldg(&g_xs[ib.x + f]);
            float a5 = __ldg(&g_xs[ib.y + f]);
            float a6 = __ldg(&g_xs[ib.z + f]);
            float a7 = __ldg(&g_xs[ib.w + f]);
            acc0 += (a0 + a1) + (a2 + a3);
            acc1 += (a4 + a5) + (a6 + a7);
        }
        for (; j < deg; j++)
            acc0 += __ldg(&g_xs[g_psrow[w * CAP + j] + f]);
        float acc = acc0 + acc1;
        for (int i = 0; i < sn; i++)
            if (g_spill_c[i] == w)
                acc += __ldg(&g_xs[g_spill_r[i] + f]);

        sagg[h][f] = acc;
        __syncthreads();
        {
            float m0 = 0.0f, m1 = 0.0f;
            #pragma unroll
            for (int k = 0; k < FIN; k++) {
                float a = sagg[h][k];
                m0 = fmaf(a, sW1[k * FMID + f],      m0);
                m1 = fmaf(a, sW1[k * FMID + f + 16], m1);
            }
            so1[h][f]      = fmaxf(fmaf(m0, d, sb1[f]),      0.0f);
            so1[h][f + 16] = fmaxf(fmaf(m1, d, sb1[f + 16]), 0.0f);
        }
        __syncthreads();
        {
            float s = 0.0f;
            #pragma unroll
            for (int k = 0; k < FMID; k++)
                s = fmaf(so1[h][k], sW2[k * FOUT + f], s);
            g_h2s[w * FOUT + f] = s * d;
        }
        // next iteration's sagg write is fenced by the first __syncthreads above
    }
    grid_barrier(2);

    // =========== phase 4: gather2 + final projection ===========
    const float fw = __ldg(&fcW[f]);
    const float bb = __ldg(&b2[f]);
    const float fb = __ldg(&fcb[0]);
    for (int g = blockIdx.x; g < NGRP; g += NBLK) {
        int w = g * 16 + h;
        const int4* adj4 = (const int4*)&g_psrow[w * CAP];
        int deg = g_degc[w];

        float acc0 = __ldg(&g_h2s[w * FOUT + f]);   // self-loop
        float acc1 = 0.0f;
        int j = 0;
        for (; j + 8 <= deg; j += 8) {
            int4 ia = __ldg(&adj4[j >> 2]);
            int4 ib = __ldg(&adj4[(j >> 2) + 1]);
            float a0 = __ldg(&g_h2s[ia.x + f]);
            float a1 = __ldg(&g_h2s[ia.y + f]);
            float a2 = __ldg(&g_h2s[ia.z + f]);
            float a3 = __ldg(&g_h2s[ia.w + f]);
            float a4 = __ldg(&g_h2s[ib.x + f]);
            float a5 = __ldg(&g_h2s[ib.y + f]);
            float a6 = __ldg(&g_h2s[ib.z + f]);
            float a7 = __ldg(&g_h2s[ib.w + f]);
            acc0 += (a0 + a1) + (a2 + a3);
            acc1 += (a4 + a5) + (a6 + a7);
        }
        for (; j < deg; j++)
            acc0 += __ldg(&g_h2s[g_psrow[w * CAP + j] + f]);
        float acc = acc0 + acc1;
        for (int i = 0; i < sn; i++)
            if (g_spill_c[i] == w)
                acc += __ldg(&g_h2s[g_spill_r[i] + f]);

        float d = g_dinv[w];
        float v = fmaxf(fmaf(acc, d, bb), 0.0f) * fw;
        #pragma unroll
        for (int s = 8; s > 0; s >>= 1)
            v += __shfl_xor_sync(0xffffffffu, v, s, 16);
        if (f == 0) out[w] = v + fb;
    }
}

// ---------------- launch ----------------
extern "C" void kernel_launch(void* const* d_in, const int* in_sizes, int n_in,
                              void* d_out, int out_size) {
    const void*  edge = d_in[0];
    const float* x    = (const float*)d_in[1];
    const float* W1   = (const float*)d_in[2];
    const float* b1   = (const float*)d_in[3];
    const float* W2   = (const float*)d_in[4];
    const float* b2   = (const float*)d_in[5];
    const float* fcW  = (const float*)d_in[6];
    const float* fcb  = (const float*)d_in[7];
    float* out = (float*)d_out;

    const int E = in_sizes[0] / 2;

    k_binit<<<1, 32>>>();
    k_mega<<<NBLK, NTHR>>>((const unsigned int*)edge, edge, E,
                           x, W1, b1, W2, b2, fcW, fcb, out);
}

// round 15
// speedup vs baseline: 1.0819x; 1.0819x over previous
#include <cuda_runtime.h>

#define N_NODES 100000
#define E_EDGES 1600000
#define FIN  16
#define FMID 32
#define FOUT 16
#define CAP  64                            // padded per-node capacity (mean deg 16)

// ---------------- device scratch ----------------
__device__ int   g_cnt[N_NODES];           // arrival counter (0 at replay start)
__device__ int   g_degc[N_NODES];          // min(deg, CAP) snapshot
__device__ float g_dinv[N_NODES];
__device__ int   g_psrow[N_NODES * CAP];   // padded adjacency, stores r*16 (premultiplied)
__device__ int   g_spill_r[E_EDGES];       // overflow (premultiplied r*16)
__device__ int   g_spill_c[E_EDGES];
__device__ int   g_spill_cursor;           // 0 at replay start
__device__ int   g_spill_n;
__device__ float g_xs [N_NODES * FIN];     // x * dinv  (layer-1 gather source, 64B rows)
__device__ float g_h2s[N_NODES * FOUT];    // (relu(o1) @ W2) * dinv

// ---------------- kernels ----------------

// Fused dtype-detect + padded-CSR build. 8 edges per thread for deep MLP.
__global__ void k_build(const unsigned int* __restrict__ words,
                        const void* __restrict__ edge_raw, int E) {
    __shared__ unsigned int s_or;
    if (threadIdx.x == 0) s_or = 0u;
    __syncthreads();
    unsigned int accd = words[2 * threadIdx.x + 1] | words[2 * (threadIdx.x + 256) + 1];
    #pragma unroll
    for (int s = 16; s > 0; s >>= 1)
        accd |= __shfl_xor_sync(0xffffffffu, accd, s);
    if ((threadIdx.x & 31) == 0) atomicOr(&s_or, accd);
    __syncthreads();
    const int is64 = (s_or == 0u) ? 1 : 0;

    int base = (blockIdx.x * blockDim.x + threadIdx.x) * 8;
    if (base >= E) return;
    int n = min(8, E - base);

    int r[8], c[8];
    if (n == 8) {
        if (is64) {
            const longlong2* p2 = (const longlong2*)edge_raw;
            #pragma unroll
            for (int q = 0; q < 4; q++) {
                longlong2 rv = __ldg(&p2[(base >> 1) + q]);
                r[q * 2] = (int)rv.x;  r[q * 2 + 1] = (int)rv.y;
            }
            #pragma unroll
            for (int q = 0; q < 4; q++) {
                longlong2 cv = __ldg(&p2[((E + base) >> 1) + q]);
                c[q * 2] = (int)cv.x;  c[q * 2 + 1] = (int)cv.y;
            }
        } else {
            const int4* p4 = (const int4*)edge_raw;
            #pragma unroll
            for (int q = 0; q < 2; q++) {
                int4 rv = __ldg(&p4[(base >> 2) + q]);
                r[q * 4] = rv.x; r[q * 4 + 1] = rv.y; r[q * 4 + 2] = rv.z; r[q * 4 + 3] = rv.w;
            }
            #pragma unroll
            for (int q = 0; q < 2; q++) {
                int4 cv = __ldg(&p4[((E + base) >> 2) + q]);
                c[q * 4] = cv.x; c[q * 4 + 1] = cv.y; c[q * 4 + 2] = cv.z; c[q * 4 + 3] = cv.w;
            }
        }
    } else {
        #pragma unroll
        for (int k = 0; k < 8; k++) if (k < n) {
            if (is64) {
                const long long* p = (const long long*)edge_raw;
                r[k] = (int)p[base + k];  c[k] = (int)p[E + base + k];
            } else {
                const int* p = (const int*)edge_raw;
                r[k] = p[base + k];       c[k] = p[E + base + k];
            }
        }
    }
    int rank[8];
    #pragma unroll
    for (int k = 0; k < 8; k++) if (k < n)
        rank[k] = atomicAdd(&g_cnt[c[k]], 1);
    #pragma unroll
    for (int k = 0; k < 8; k++) if (k < n) {
        if (rank[k] < CAP) {
            g_psrow[c[k] * CAP + rank[k]] = r[k] * 16;    // premultiplied
        } else {                                          // correctness fallback
            int s = atomicAdd(&g_spill_cursor, 1);
            g_spill_c[s] = c[k];
            g_spill_r[s] = r[k] * 16;
        }
    }
}

// xs = x * dinv ; degree snapshot + counter reset. 16 lanes per node.
__global__ void k_scale(const float* __restrict__ x) {
    int idx = blockIdx.x * blockDim.x + threadIdx.x;
    if (idx == 0) {
        g_spill_n = g_spill_cursor;
        g_spill_cursor = 0;
    }
    if (idx >= N_NODES * FIN) return;
    int i = idx >> 4;
    int f = idx & 15;
    int deg = g_cnt[i];                     // all 16 lanes read before lane-0 resets
    float d = rsqrtf((float)(deg + 1));     // +1 self-loop
    __syncwarp();
    if (f == 0) {
        g_dinv[i] = d;
        g_degc[i] = min(deg, CAP);
        g_cnt[i]  = 0;                      // ready for next replay
    }
    g_xs[idx] = __ldg(&x[idx]) * d;
}

// Fused gather1 + W1 + relu + W2 (aggregation in 16-dim input space).
// Half-warp per node, lane = input feature. Premultiplied indices: addr = r16 + f.
__global__ void k_gather1_lin12(const float* __restrict__ W1,
                                const float* __restrict__ b1,
                                const float* __restrict__ W2) {
    __shared__ float sW1[FIN * FMID];
    __shared__ float sW2[FMID * FOUT];
    __shared__ float sb1[FMID];
    __shared__ float sagg[16][FIN];
    __shared__ float so1[16][FMID];
    for (int t = threadIdx.x; t < FIN * FMID; t += blockDim.x) {
        sW1[t] = W1[t];
        sW2[t] = W2[t];
    }
    for (int t = threadIdx.x; t < FMID; t += blockDim.x) sb1[t] = b1[t];
    __syncthreads();

    int w = (blockIdx.x * blockDim.x + threadIdx.x) >> 4;   // node (grid exact)
    int f = threadIdx.x & 15;
    int h = (threadIdx.x >> 4) & 15;

    const int4* adj4 = (const int4*)&g_psrow[w * CAP];
    int deg = g_degc[w];
    float d = g_dinv[w];

    float acc0 = g_xs[w * FIN + f];         // self-loop
    float acc1 = 0.0f;
    int j = 0;
    for (; j + 8 <= deg; j += 8) {
        int4 ia = __ldg(&adj4[j >> 2]);
        int4 ib = __ldg(&adj4[(j >> 2) + 1]);
        float a0 = __ldg(&g_xs[ia.x + f]);
        float a1 = __ldg(&g_xs[ia.y + f]);
        float a2 = __ldg(&g_xs[ia.z + f]);
        float a3 = __ldg(&g_xs[ia.w + f]);
        float a4 = __ldg(&g_xs[ib.x + f]);
        float a5 = __ldg(&g_xs[ib.y + f]);
        float a6 = __ldg(&g_xs[ib.z + f]);
        float a7 = __ldg(&g_xs[ib.w + f]);
        acc0 += (a0 + a1) + (a2 + a3);
        acc1 += (a4 + a5) + (a6 + a7);
    }
    for (; j < deg; j++)
        acc0 += __ldg(&g_xs[g_psrow[w * CAP + j] + f]);
    float acc = acc0 + acc1;

    int sn = g_spill_n;                     // 0 for this input; correctness path
    for (int i = 0; i < sn; i++)
        if (g_spill_c[i] == w)
            acc += __ldg(&g_xs[g_spill_r[i] + f]);

    sagg[h][f] = acc;
    __syncthreads();

    {
        float m0 = 0.0f, m1 = 0.0f;
        #pragma unroll
        for (int k = 0; k < FIN; k++) {
            float a = sagg[h][k];
            m0 = fmaf(a, sW1[k * FMID + f],      m0);
            m1 = fmaf(a, sW1[k * FMID + f + 16], m1);
        }
        so1[h][f]      = fmaxf(fmaf(m0, d, sb1[f]),      0.0f);
        so1[h][f + 16] = fmaxf(fmaf(m1, d, sb1[f + 16]), 0.0f);
    }
    __syncthreads();

    {
        float s = 0.0f;
        #pragma unroll
        for (int k = 0; k < FMID; k++)
            s = fmaf(so1[h][k], sW2[k * FOUT + f], s);
        g_h2s[w * FOUT + f] = s * d;
    }
}

// Fused gather2 + final. Half-warp per node, lane = feature.
// Premultiplied indices: addr = r16 + f.
__global__ void k_gather2_final(const float* __restrict__ fcW,
                                const float* __restrict__ fcb,
                                const float* __restrict__ b2,
                                float* __restrict__ out) {
    int h = (blockIdx.x * blockDim.x + threadIdx.x) >> 4;
    if (h >= N_NODES) return;
    int f = threadIdx.x & 15;

    const int4* adj4 = (const int4*)&g_psrow[h * CAP];
    int deg = g_degc[h];
    float acc0 = __ldg(&g_h2s[h * FOUT + f]);   // self-loop
    float acc1 = 0.0f;
    int j = 0;
    for (; j + 8 <= deg; j += 8) {
        int4 ia = __ldg(&adj4[j >> 2]);
        int4 ib = __ldg(&adj4[(j >> 2) + 1]);
        float a0 = __ldg(&g_h2s[ia.x + f]);
        float a1 = __ldg(&g_h2s[ia.y + f]);
        float a2 = __ldg(&g_h2s[ia.z + f]);
        float a3 = __ldg(&g_h2s[ia.w + f]);
        float a4 = __ldg(&g_h2s[ib.x + f]);
        float a5 = __ldg(&g_h2s[ib.y + f]);
        float a6 = __ldg(&g_h2s[ib.z + f]);
        float a7 = __ldg(&g_h2s[ib.w + f]);
        acc0 += (a0 + a1) + (a2 + a3);
        acc1 += (a4 + a5) + (a6 + a7);
    }
    for (; j < deg; j++)
        acc0 += __ldg(&g_h2s[g_psrow[h * CAP + j] + f]);
    float acc = acc0 + acc1;

    int sn = g_spill_n;
    for (int i = 0; i < sn; i++)
        if (g_spill_c[i] == h)
            acc += __ldg(&g_h2s[g_spill_r[i] + f]);

    float d = g_dinv[h];
    float v = fmaxf(fmaf(acc, d, __ldg(&b2[f])), 0.0f) * __ldg(&fcW[f]);
    #pragma unroll
    for (int s = 8; s > 0; s >>= 1)
        v += __shfl_xor_sync(0xffffffffu, v, s, 16);
    if (f == 0) out[h] = v + __ldg(&fcb[0]);
}

// ---------------- launch ----------------
extern "C" void kernel_launch(void* const* d_in, const int* in_sizes, int n_in,
                              void* d_out, int out_size) {
    const void*  edge = d_in[0];
    const float* x    = (const float*)d_in[1];
    const float* W1   = (const float*)d_in[2];
    const float* b1   = (const float*)d_in[3];
    const float* W2   = (const float*)d_in[4];
    const float* b2   = (const float*)d_in[5];
    const float* fcW  = (const float*)d_in[6];
    const float* fcb  = (const float*)d_in[7];
    float* out = (float*)d_out;

    const int E = in_sizes[0] / 2;
    const int T = 256;

    k_build         <<<(E / 8 + T - 1) / T, T>>>((const unsigned int*)edge, edge, E);
    k_scale         <<<(N_NODES * FIN + T - 1) / T, T>>>(x);
    k_gather1_lin12 <<<(N_NODES * FIN + T - 1) / T, T>>>(W1, b1, W2);
    k_gather2_final <<<(N_NODES * FOUT + T - 1) / T, T>>>(fcW, fcb, b2, out);
}